// round 15
// baseline (speedup 1.0000x reference)
#include <cuda_runtime.h>
#include <cuda_bf16.h>
#include <math.h>

// ---------------------------------------------------------------------------
// IGAB block, B=4, C=128, H=W=256, window 8x8, heads=8, head_dim=16, HIDDEN=512
//   k0: pack all weights into fragment-ordered bf16 hi/lo u32 arrays
//   k1: 512 thr: LN1 + QKV(MMA, W frags via LDG) + gate + attn + proj
//   k2: 512 thr: LN2 + W1 + GELU (W frags via LDG, no W smem)
//   k3: depthwise 3x3 + bias + GELU (4px/thread)
//   k4: 512 thr: W2 + bias + residual (cp.async X, W frags via LDG)
// ---------------------------------------------------------------------------

#define HW 65536
#define NPLANE 256

__device__ float g_h1[(size_t)4 * 512 * HW];
__device__ __nv_bfloat16 g_h2h[(size_t)4 * 512 * HW];
__device__ __nv_bfloat16 g_h2l[(size_t)4 * 512 * HW];
// fragment-packed weights (u32 = 2 bf16)
__device__ unsigned int g_qkvpk[49152];   // 6ch*8ks*4mw*32l*8
__device__ unsigned int g_pwpk[16384];    // 2ch*8ks*4mw*32l*8
__device__ unsigned int g_w1pk[65536];    // 4ch*8ks*4mg*32l*16
__device__ unsigned int g_w2pk[65536];    // 4kc*8ks*4mg*32l*16

typedef unsigned long long u64;
typedef unsigned int u32;
typedef __nv_bfloat16 bf16;

__device__ __forceinline__ u64 ffma2(u64 a, u64 b, u64 c) {
    u64 d;
    asm("fma.rn.f32x2 %0, %1, %2, %3;" : "=l"(d) : "l"(a), "l"(b), "l"(c));
    return d;
}
__device__ __forceinline__ float2 unpack2(u64 v) {
    unsigned lo, hi;
    asm("mov.b64 {%0, %1}, %2;" : "=r"(lo), "=r"(hi) : "l"(v));
    return make_float2(__uint_as_float(lo), __uint_as_float(hi));
}
__device__ __forceinline__ float gelu_exact(float v) {
    return 0.5f * v * (1.0f + erff(v * 0.70710678118654752f));
}
__device__ __forceinline__ void mma16816(float* c, const u32* a, u32 b0, u32 b1) {
    asm volatile(
        "mma.sync.aligned.m16n8k16.row.col.f32.bf16.bf16.f32 "
        "{%0,%1,%2,%3},{%4,%5,%6,%7},{%8,%9},{%0,%1,%2,%3};"
        : "+f"(c[0]), "+f"(c[1]), "+f"(c[2]), "+f"(c[3])
        : "r"(a[0]), "r"(a[1]), "r"(a[2]), "r"(a[3]), "r"(b0), "r"(b1));
}
__device__ __forceinline__ void ldsm4t(u32& d0, u32& d1, u32& d2, u32& d3, u32 a) {
    asm volatile("ldmatrix.sync.aligned.m8n8.x4.trans.shared.b16 {%0,%1,%2,%3},[%4];"
                 : "=r"(d0), "=r"(d1), "=r"(d2), "=r"(d3) : "r"(a));
}
__device__ __forceinline__ void split_bf16(float v, bf16& h, bf16& l) {
    h = __float2bfloat16(v);
    l = __float2bfloat16(v - __bfloat162float(h));
}
__device__ __forceinline__ u32 pack_split(float a, float b, int isLo) {
    bf16 ah, al, bh, bl;
    split_bf16(a, ah, al);
    split_bf16(b, bh, bl);
    u32 x = isLo ? __bfloat16_as_ushort(al) : __bfloat16_as_ushort(ah);
    u32 y = isLo ? __bfloat16_as_ushort(bl) : __bfloat16_as_ushort(bh);
    return x | (y << 16);
}
__device__ __forceinline__ void cpasync16(u32 smem_addr, const void* gptr) {
    asm volatile("cp.async.ca.shared.global [%0], [%1], 16;"
                 :: "r"(smem_addr), "l"(gptr) : "memory");
}
#define CP_COMMIT() asm volatile("cp.async.commit_group;" ::: "memory")
#define CP_WAIT0()  asm volatile("cp.async.wait_group 0;" ::: "memory")

// ======================= kernel 0: weight fragment packing =================
__global__ __launch_bounds__(256)
void k0_prep(const float* __restrict__ w1, const float* __restrict__ w2,
             const float* __restrict__ qkvw, const float* __restrict__ pw)
{
    int i = blockIdx.x * 256 + threadIdx.x;     // 196608 total
    if (i < 49152) {
        // QKV, type A: 8 u32/lane  (j 0-3 hi, 4-7 lo)
        int j = i & 7, l = (i >> 3) & 31, mw = (i >> 8) & 3, ks = (i >> 10) & 7, ch = i >> 13;
        int row = ch * 64 + mw * 16 + (l >> 2) + (j & 1) * 8;
        int kc = ks * 16 + ((j >> 1) & 1) * 8 + (l & 3) * 2;
        g_qkvpk[i] = pack_split(qkvw[row * 128 + kc], qkvw[row * 128 + kc + 1], j >> 2);
    } else if (i < 65536) {
        int k = i - 49152;  // proj, type A
        int j = k & 7, l = (k >> 3) & 31, mw = (k >> 8) & 3, ks = (k >> 10) & 7, ch = k >> 13;
        int row = ch * 64 + mw * 16 + (l >> 2) + (j & 1) * 8;
        int kc = ks * 16 + ((j >> 1) & 1) * 8 + (l & 3) * 2;
        g_pwpk[k] = pack_split(pw[row * 128 + kc], pw[row * 128 + kc + 1], j >> 2);
    } else if (i < 131072) {
        int k = i - 65536;  // w1 [512][128], type B: 16 u32/lane
        int j = k & 15, l = (k >> 4) & 31, mg = (k >> 9) & 3, ks = (k >> 11) & 7, ch = k >> 14;
        int jj = j & 3, mt = (j >> 2) & 1, isLo = j >> 3;
        int row = ch * 128 + mg * 32 + mt * 16 + (l >> 2) + (jj & 1) * 8;
        int kc = ks * 16 + ((jj >> 1) & 1) * 8 + (l & 3) * 2;
        g_w1pk[k] = pack_split(w1[row * 128 + kc], w1[row * 128 + kc + 1], isLo);
    } else {
        int k = i - 131072; // w2 [128][512], type B
        int j = k & 15, l = (k >> 4) & 31, mg = (k >> 9) & 3, ks = (k >> 11) & 7, ch = k >> 14;
        int jj = j & 3, mt = (j >> 2) & 1, isLo = j >> 3;
        int row = mg * 32 + mt * 16 + (l >> 2) + (jj & 1) * 8;
        int kc = ch * 128 + ks * 16 + ((jj >> 1) & 1) * 8 + (l & 3) * 2;
        g_w2pk[k] = pack_split(w2[row * 512 + kc], w2[row * 512 + kc + 1], isLo);
    }
}

// ======================= kernel 1: attention block, 512 thr ================
// smem byte layout (212224 total):
//   Af f32[128][68] @0 | Xh bf16[128][72] @34816 | Xl @53248
//   Sf[2] f32[64][68] @71680 (+hb*17408)
//   Qf f32[128][68] @106496 | Kf @141312 | Vf @176128
//   L0 @210944 | MU @211200 | RS @211456 | DEN[128] @211712
#define SM1_BYTES 212224

__global__ __launch_bounds__(512, 1)
void k1_attn(const float* __restrict__ x, const float* __restrict__ l0,
             const float* __restrict__ n1w, const float* __restrict__ n1b,
             const float* __restrict__ gw, const float* __restrict__ gb,
             const float* __restrict__ pb, float* __restrict__ outp)
{
    extern __shared__ float sm[];
    char* smcc = (char*)sm;
    float* Af = sm;
    bf16* Xh = (bf16*)(smcc + 34816);
    bf16* Xl = (bf16*)(smcc + 53248);
    float* Sf = sm + 17920;
    float* Qf = sm + 26624;
    float* Kf = sm + 35328;
    float* Vf = sm + 44032;
    float* L0v = sm + 52736;
    float* MUv = sm + 52800;
    float* RSv = sm + 52864;
    float* DENv = sm + 52928;

    const int tid = threadIdx.x;
    const int wi = blockIdx.x;
    const int b  = wi >> 10;
    const int hi = (wi >> 5) & 31;
    const int wj = wi & 31;
    const int base_pix = (hi * 8) * NPLANE + wj * 8;
    const float* xb = x + (size_t)b * 128 * HW;

    #pragma unroll
    for (int it = 0; it < 16; ++it) {
        int idx = tid + it * 512;
        int c = idx >> 6, p = idx & 63;
        Af[c * 68 + p] = xb[c * HW + base_pix + (p >> 3) * NPLANE + (p & 7)];
    }
    if (tid < 64) {
        int p = tid;
        L0v[p] = l0[(size_t)b * HW + base_pix + (p >> 3) * NPLANE + (p & 7)];
    }
    __syncthreads();

    {   // LN1 stats: 8 threads/pixel
        int p = tid >> 3, part = tid & 7;
        float s = 0.f, sq = 0.f;
        #pragma unroll
        for (int c = part * 16; c < part * 16 + 16; ++c) {
            float v = Af[c * 68 + p];
            s += v; sq += v * v;
        }
        s  += __shfl_xor_sync(0xffffffffu, s, 1);
        sq += __shfl_xor_sync(0xffffffffu, sq, 1);
        s  += __shfl_xor_sync(0xffffffffu, s, 2);
        sq += __shfl_xor_sync(0xffffffffu, sq, 2);
        s  += __shfl_xor_sync(0xffffffffu, s, 4);
        sq += __shfl_xor_sync(0xffffffffu, sq, 4);
        if (part == 0) {
            float mu = s * (1.f / 128.f);
            float var = sq * (1.f / 128.f) - mu * mu;
            MUv[p] = mu;
            RSv[p] = rsqrtf(var + 1e-6f);
        }
    }
    __syncthreads();
    #pragma unroll
    for (int it = 0; it < 16; ++it) {
        int idx = tid + it * 512;
        int c = idx >> 6, p = idx & 63;
        float xn = n1w[c] * (Af[c * 68 + p] - MUv[p]) * RSv[p] + n1b[c];
        bf16 h, l;
        split_bf16(xn, h, l);
        Xh[c * 72 + p] = h;
        Xl[c * 72 + p] = l;
    }
    __syncthreads();

    const int lane = tid & 31;
    const int warp = tid >> 5;
    const int g = lane >> 2, tg = lane & 3;
    const int mwarp = warp >> 2;
    const int nwarp = warp & 3;
    const int laneX = (lane & 15) * 144 + ((lane >> 4) << 4);

    const u32 smXh = (u32)__cvta_generic_to_shared(Xh);
    const u32 smXl = (u32)__cvta_generic_to_shared(Xl);

    // ---- QKV: 6 chunks, W fragments via LDG (L2-resident), no barriers ----
    for (int ch = 0; ch < 6; ++ch) {
        float acc[2][4];
        #pragma unroll
        for (int nt = 0; nt < 2; ++nt)
            #pragma unroll
            for (int q = 0; q < 4; ++q) acc[nt][q] = 0.f;

        #pragma unroll
        for (int ks = 0; ks < 8; ++ks) {
            const uint4* wp = (const uint4*)&g_qkvpk[(ch * 8 + ks) * 1024 + mwarp * 256 + lane * 8];
            uint4 AH = wp[0], AL = wp[1];
            u32 ah[4] = {AH.x, AH.y, AH.z, AH.w};
            u32 al[4] = {AL.x, AL.y, AL.z, AL.w};
            int n0 = nwarp * 16;
            u32 bh[4], bl[4];
            ldsm4t(bh[0], bh[1], bh[2], bh[3], smXh + laneX + ks * 16 * 144 + n0 * 2);
            ldsm4t(bl[0], bl[1], bl[2], bl[3], smXl + laneX + ks * 16 * 144 + n0 * 2);
            mma16816(acc[0], ah, bh[0], bh[1]);
            mma16816(acc[1], ah, bh[2], bh[3]);
            mma16816(acc[0], ah, bl[0], bl[1]);
            mma16816(acc[1], ah, bl[2], bl[3]);
            mma16816(acc[0], al, bh[0], bh[1]);
            mma16816(acc[1], al, bh[2], bh[3]);
        }

        float* dst = (ch < 2) ? Qf : (ch < 4) ? Kf : Vf;
        int rloc = (ch & 1) * 64 + mwarp * 16;
        int r0 = rloc + g, r1 = rloc + g + 8;
        if (ch < 2) {
            float gw0 = gw[r0], gb0 = gb[r0];
            float gw1 = gw[r1], gb1 = gb[r1];
            #pragma unroll
            for (int nt = 0; nt < 2; ++nt) {
                int col = nwarp * 16 + nt * 8 + tg * 2;
                float la = L0v[col], lb = L0v[col + 1];
                float s00 = 1.f / (1.f + __expf(-(la * gw0 + gb0)));
                float s01 = 1.f / (1.f + __expf(-(lb * gw0 + gb0)));
                float s10 = 1.f / (1.f + __expf(-(la * gw1 + gb1)));
                float s11 = 1.f / (1.f + __expf(-(lb * gw1 + gb1)));
                *(float2*)&dst[r0 * 68 + col] = make_float2(acc[nt][0] * s00, acc[nt][1] * s01);
                *(float2*)&dst[r1 * 68 + col] = make_float2(acc[nt][2] * s10, acc[nt][3] * s11);
            }
        } else {
            #pragma unroll
            for (int nt = 0; nt < 2; ++nt) {
                int col = nwarp * 16 + nt * 8 + tg * 2;
                *(float2*)&dst[r0 * 68 + col] = make_float2(acc[nt][0], acc[nt][1]);
                *(float2*)&dst[r1 * 68 + col] = make_float2(acc[nt][2], acc[nt][3]);
            }
        }
    }
    __syncthreads();

    // ---- window attention (FFMA2), 2 heads concurrent ----
    const int hb = tid >> 8;
    const int t = tid & 255;
    float* Sfh = Sf + hb * 4352;
    for (int hp = 0; hp < 4; ++hp) {
        const int cb = (2 * hp + hb) * 16;
        {
            const int tx = t & 15, ty = t >> 4;
            u64 acc2[2][4];
            #pragma unroll
            for (int i = 0; i < 2; ++i)
                #pragma unroll
                for (int j = 0; j < 4; ++j) acc2[i][j] = 0ull;
            #pragma unroll
            for (int d = 0; d < 16; ++d) {
                ulonglong2 qv = *(const ulonglong2*)&Qf[(cb + d) * 68 + 4 * tx];
                #pragma unroll
                for (int j = 0; j < 4; ++j) {
                    float kvs = Kf[(cb + d) * 68 + 4 * ty + j];
                    u64 kp;
                    asm("mov.b64 %0, {%1, %1};" : "=l"(kp) : "r"(__float_as_uint(kvs)));
                    acc2[0][j] = ffma2(qv.x, kp, acc2[0][j]);
                    acc2[1][j] = ffma2(qv.y, kp, acc2[1][j]);
                }
            }
            #pragma unroll
            for (int a = 0; a < 2; ++a)
                #pragma unroll
                for (int j = 0; j < 4; ++j) {
                    float2 f = unpack2(acc2[a][j]);
                    Sfh[(4 * tx + 2 * a) * 68 + 4 * ty + j] = f.x * 0.25f;
                    Sfh[(4 * tx + 2 * a + 1) * 68 + 4 * ty + j] = f.y * 0.25f;
                }
        }
        __syncthreads();
        {
            int r = t >> 2, part = t & 3;
            float m = -1e30f;
            #pragma unroll
            for (int kk = part * 16; kk < part * 16 + 16; ++kk)
                m = fmaxf(m, Sfh[r * 68 + kk]);
            m = fmaxf(m, __shfl_xor_sync(0xffffffffu, m, 1));
            m = fmaxf(m, __shfl_xor_sync(0xffffffffu, m, 2));
            float s = 0.f;
            #pragma unroll
            for (int kk = part * 16; kk < part * 16 + 16; ++kk) {
                float e = __expf(Sfh[r * 68 + kk] - m);
                Sfh[r * 68 + kk] = e;
                s += e;
            }
            s += __shfl_xor_sync(0xffffffffu, s, 1);
            s += __shfl_xor_sync(0xffffffffu, s, 2);
            if (part == 0) DENv[hb * 64 + r] = 1.f / s;
        }
        __syncthreads();
        {
            int pq = t >> 2, dg = t & 3;
            const u64* Srow = (const u64*)&Sfh[pq * 68];
            const u64* V0 = (const u64*)&Vf[(cb + 4 * dg + 0) * 68];
            const u64* V1 = (const u64*)&Vf[(cb + 4 * dg + 1) * 68];
            const u64* V2 = (const u64*)&Vf[(cb + 4 * dg + 2) * 68];
            const u64* V3 = (const u64*)&Vf[(cb + 4 * dg + 3) * 68];
            u64 a0 = 0ull, a1 = 0ull, a2 = 0ull, a3 = 0ull;
            #pragma unroll 8
            for (int kk = 0; kk < 32; ++kk) {
                u64 prp = Srow[kk];
                a0 = ffma2(prp, V0[kk], a0);
                a1 = ffma2(prp, V1[kk], a1);
                a2 = ffma2(prp, V2[kk], a2);
                a3 = ffma2(prp, V3[kk], a3);
            }
            float dn = DENv[hb * 64 + pq];
            float2 f0 = unpack2(a0), f1 = unpack2(a1), f2 = unpack2(a2), f3 = unpack2(a3);
            bf16 h_, l_;
            split_bf16((f0.x + f0.y) * dn, h_, l_);
            Xh[(cb + 4 * dg + 0) * 72 + pq] = h_; Xl[(cb + 4 * dg + 0) * 72 + pq] = l_;
            split_bf16((f1.x + f1.y) * dn, h_, l_);
            Xh[(cb + 4 * dg + 1) * 72 + pq] = h_; Xl[(cb + 4 * dg + 1) * 72 + pq] = l_;
            split_bf16((f2.x + f2.y) * dn, h_, l_);
            Xh[(cb + 4 * dg + 2) * 72 + pq] = h_; Xl[(cb + 4 * dg + 2) * 72 + pq] = l_;
            split_bf16((f3.x + f3.y) * dn, h_, l_);
            Xh[(cb + 4 * dg + 3) * 72 + pq] = h_; Xl[(cb + 4 * dg + 3) * 72 + pq] = l_;
        }
        __syncthreads();
    }

    // ---- proj (MMA) + bias + residual, W via LDG, no barriers ----
    for (int ch = 0; ch < 2; ++ch) {
        float acc[2][4];
        #pragma unroll
        for (int nt = 0; nt < 2; ++nt)
            #pragma unroll
            for (int q = 0; q < 4; ++q) acc[nt][q] = 0.f;

        #pragma unroll
        for (int ks = 0; ks < 8; ++ks) {
            const uint4* wp = (const uint4*)&g_pwpk[(ch * 8 + ks) * 1024 + mwarp * 256 + lane * 8];
            uint4 AH = wp[0], AL = wp[1];
            u32 ah[4] = {AH.x, AH.y, AH.z, AH.w};
            u32 al[4] = {AL.x, AL.y, AL.z, AL.w};
            int n0 = nwarp * 16;
            u32 bh[4], bl[4];
            ldsm4t(bh[0], bh[1], bh[2], bh[3], smXh + laneX + ks * 16 * 144 + n0 * 2);
            ldsm4t(bl[0], bl[1], bl[2], bl[3], smXl + laneX + ks * 16 * 144 + n0 * 2);
            mma16816(acc[0], ah, bh[0], bh[1]);
            mma16816(acc[1], ah, bh[2], bh[3]);
            mma16816(acc[0], ah, bl[0], bl[1]);
            mma16816(acc[1], ah, bl[2], bl[3]);
            mma16816(acc[0], al, bh[0], bh[1]);
            mma16816(acc[1], al, bh[2], bh[3]);
        }

        int r0 = mwarp * 16 + g, r1 = r0 + 8;
        int o0 = ch * 64 + r0, o1 = ch * 64 + r1;
        float pb0 = pb[o0], pb1 = pb[o1];
        float* op0 = outp + (size_t)(b * 128 + o0) * HW + base_pix;
        float* op1 = outp + (size_t)(b * 128 + o1) * HW + base_pix;
        #pragma unroll
        for (int nt = 0; nt < 2; ++nt) {
            int col = nwarp * 16 + nt * 8 + tg * 2;
            int goff = ((col >> 3) * NPLANE) + (col & 7);
            float2 v0 = make_float2(acc[nt][0] + pb0 + Af[o0 * 68 + col],
                                    acc[nt][1] + pb0 + Af[o0 * 68 + col + 1]);
            float2 v1 = make_float2(acc[nt][2] + pb1 + Af[o1 * 68 + col],
                                    acc[nt][3] + pb1 + Af[o1 * 68 + col + 1]);
            *(float2*)&op0[goff] = v0;
            *(float2*)&op1[goff] = v1;
        }
    }
}

// ======================= kernel 2: LN2 + W1 + GELU, 512 thr ================
// smem: Xh bf16[128][136] @0 | Xl @34816 | Xf f32[128][132] @69632
//       MU @137216 | RS @137728
#define SM2_BYTES 138240

__global__ __launch_bounds__(512, 1)
void k2_ffn1(const float* __restrict__ inp, const float* __restrict__ n2w,
             const float* __restrict__ n2b, const float* __restrict__ b1)
{
    extern __shared__ char smc[];
    bf16* Xh = (bf16*)smc;
    bf16* Xl = (bf16*)(smc + 34816);
    float* Xf = (float*)(smc + 69632);
    float* MU = (float*)(smc + 137216);
    float* RS = (float*)(smc + 137728);
    const u32 smbase = (u32)__cvta_generic_to_shared(smc);

    const int tid = threadIdx.x;
    const int pg = blockIdx.x * 128;
    const int b = pg >> 16;
    const int pix = pg & 65535;
    const float* ib = inp + (size_t)b * 128 * HW + pix;

    #pragma unroll
    for (int it = 0; it < 32; ++it) {
        int idx = tid + it * 512;
        int c = idx >> 7, p = idx & 127;
        Xf[c * 132 + p] = ib[c * HW + p];
    }
    __syncthreads();
    {
        int p = tid >> 2, part = tid & 3;
        float s = 0.f, sq = 0.f;
        #pragma unroll
        for (int c = part * 32; c < part * 32 + 32; ++c) {
            float v = Xf[c * 132 + p];
            s += v; sq += v * v;
        }
        s  += __shfl_xor_sync(0xffffffffu, s, 1);
        sq += __shfl_xor_sync(0xffffffffu, sq, 1);
        s  += __shfl_xor_sync(0xffffffffu, s, 2);
        sq += __shfl_xor_sync(0xffffffffu, sq, 2);
        if (part == 0) {
            float mu = s * (1.f / 128.f);
            float var = sq * (1.f / 128.f) - mu * mu;
            MU[p] = mu;
            RS[p] = rsqrtf(var + 1e-6f);
        }
    }
    __syncthreads();
    #pragma unroll
    for (int it = 0; it < 32; ++it) {
        int idx = tid + it * 512;
        int c = idx >> 7, p = idx & 127;
        float xn = n2w[c] * (Xf[c * 132 + p] - MU[p]) * RS[p] + n2b[c];
        bf16 h, l;
        split_bf16(xn, h, l);
        Xh[c * 136 + p] = h;
        Xl[c * 136 + p] = l;
    }
    __syncthreads();

    const int lane = tid & 31;
    const int warp = tid >> 5;
    const int g = lane >> 2, tg = lane & 3;
    const int mg = warp >> 2;
    const int mbase = mg * 32;
    const int nbase = (warp & 3) * 32;
    const int laneoff = (lane & 15) * 272 + ((lane >> 4) << 4);
    const u32 smXh = smbase;
    const u32 smXl = smbase + 34816;

    for (int och = 0; och < 4; ++och) {
        float acc[2][4][4];
        #pragma unroll
        for (int mt = 0; mt < 2; ++mt)
            #pragma unroll
            for (int nt = 0; nt < 4; ++nt)
                #pragma unroll
                for (int q = 0; q < 4; ++q) acc[mt][nt][q] = 0.f;

        #pragma unroll
        for (int ks = 0; ks < 8; ++ks) {
            const uint4* wp = (const uint4*)&g_w1pk[(och * 8 + ks) * 2048 + mg * 512 + lane * 16];
            uint4 H0 = wp[0], H1 = wp[1], L0_ = wp[2], L1 = wp[3];
            u32 ah[2][4] = {{H0.x, H0.y, H0.z, H0.w}, {H1.x, H1.y, H1.z, H1.w}};
            u32 al[2][4] = {{L0_.x, L0_.y, L0_.z, L0_.w}, {L1.x, L1.y, L1.z, L1.w}};
            #pragma unroll
            for (int ntp = 0; ntp < 2; ++ntp) {
                int n0 = nbase + ntp * 16;
                u32 bh[4], bl[4];
                ldsm4t(bh[0], bh[1], bh[2], bh[3],
                       smXh + laneoff + ks * 16 * 272 + n0 * 2);
                ldsm4t(bl[0], bl[1], bl[2], bl[3],
                       smXl + laneoff + ks * 16 * 272 + n0 * 2);
                #pragma unroll
                for (int mt = 0; mt < 2; ++mt) {
                    mma16816(acc[mt][2 * ntp],     ah[mt], bh[0], bh[1]);
                    mma16816(acc[mt][2 * ntp + 1], ah[mt], bh[2], bh[3]);
                    mma16816(acc[mt][2 * ntp],     ah[mt], bl[0], bl[1]);
                    mma16816(acc[mt][2 * ntp + 1], ah[mt], bl[2], bl[3]);
                    mma16816(acc[mt][2 * ntp],     al[mt], bh[0], bh[1]);
                    mma16816(acc[mt][2 * ntp + 1], al[mt], bh[2], bh[3]);
                }
            }
        }

        #pragma unroll
        for (int mt = 0; mt < 2; ++mt) {
            int r = mbase + mt * 16 + g;
            int o0 = och * 128 + r, o1 = o0 + 8;
            float bv0 = b1[o0], bv1 = b1[o1];
            float* p0 = &g_h1[(size_t)(b * 512 + o0) * HW + pix];
            float* p1 = &g_h1[(size_t)(b * 512 + o1) * HW + pix];
            #pragma unroll
            for (int nt = 0; nt < 4; ++nt) {
                int col = nbase + nt * 8 + tg * 2;
                float2 v0 = make_float2(gelu_exact(acc[mt][nt][0] + bv0),
                                        gelu_exact(acc[mt][nt][1] + bv0));
                float2 v1 = make_float2(gelu_exact(acc[mt][nt][2] + bv1),
                                        gelu_exact(acc[mt][nt][3] + bv1));
                *(float2*)&p0[col] = v0;
                *(float2*)&p1[col] = v1;
            }
        }
    }
}

// ======================= kernel 3: dw3x3 + GELU ============================
__global__ __launch_bounds__(256)
void k3_dw(const float* __restrict__ dw, const float* __restrict__ dwb)
{
    const int blk = blockIdx.x;
    const int plane = blk >> 6;
    const int ch = plane & 511;
    const int rg = blk & 63;
    const int tid = threadIdx.x;
    const int y = rg * 4 + (tid >> 6);
    const int xc = (tid & 63) * 4;
    const float* ip = g_h1 + (size_t)plane * HW;

    float w[9];
    #pragma unroll
    for (int i = 0; i < 9; ++i) w[i] = dw[ch * 9 + i];
    const float bias = dwb[ch];

    float v[3][6];
    #pragma unroll
    for (int dy = 0; dy < 3; ++dy) {
        int yy = y + dy - 1;
        if (yy >= 0 && yy < 256) {
            const float* row = ip + yy * NPLANE + xc;
            float4 m = *(const float4*)row;
            v[dy][1] = m.x; v[dy][2] = m.y; v[dy][3] = m.z; v[dy][4] = m.w;
            v[dy][0] = (xc > 0) ? row[-1] : 0.f;
            v[dy][5] = (xc < 252) ? row[4] : 0.f;
        } else {
            #pragma unroll
            for (int i = 0; i < 6; ++i) v[dy][i] = 0.f;
        }
    }

    bf16 hh[4], ll[4];
    #pragma unroll
    for (int p = 0; p < 4; ++p) {
        float s = bias;
        #pragma unroll
        for (int dy = 0; dy < 3; ++dy)
            s += w[dy * 3 + 0] * v[dy][p] + w[dy * 3 + 1] * v[dy][p + 1]
               + w[dy * 3 + 2] * v[dy][p + 2];
        float r = gelu_exact(s);
        split_bf16(r, hh[p], ll[p]);
    }

    uint2 ph, pl;
    ph.x = (u32)__bfloat16_as_ushort(hh[0]) | ((u32)__bfloat16_as_ushort(hh[1]) << 16);
    ph.y = (u32)__bfloat16_as_ushort(hh[2]) | ((u32)__bfloat16_as_ushort(hh[3]) << 16);
    pl.x = (u32)__bfloat16_as_ushort(ll[0]) | ((u32)__bfloat16_as_ushort(ll[1]) << 16);
    pl.y = (u32)__bfloat16_as_ushort(ll[2]) | ((u32)__bfloat16_as_ushort(ll[3]) << 16);
    size_t off = (size_t)plane * HW + y * NPLANE + xc;
    *(uint2*)&g_h2h[off] = ph;
    *(uint2*)&g_h2l[off] = pl;
}

// ======================= kernel 4: W2 + residual, 512 thr ==================
// smem: X0h@0 X0l@34816 | X1h@69632 X1l@104448
#define SM4_BYTES 139264

__global__ __launch_bounds__(512, 1)
void k4_ffn2(const float* __restrict__ b2, float* __restrict__ io)
{
    extern __shared__ char smc[];
    const u32 smbase = (u32)__cvta_generic_to_shared(smc);
    const u32 smX[2] = {smbase, smbase + 69632};

    const int tid = threadIdx.x;
    const int pg = blockIdx.x * 128;
    const int b = pg >> 16;
    const int pix = pg & 65535;

    const int c16 = tid & 15;
    const int xrow = tid >> 4;

    auto copyX = [&](int kc, int sel) {
        const char* srcH = (const char*)g_h2h +
            ((size_t)(b * 512 + kc * 128)) * (HW * 2) + (size_t)pix * 2;
        const char* srcL = (const char*)g_h2l +
            ((size_t)(b * 512 + kc * 128)) * (HW * 2) + (size_t)pix * 2;
        u32 dst = smX[sel];
        #pragma unroll
        for (int it = 0; it < 4; ++it) {
            int k = xrow + it * 32;
            cpasync16(dst + k * 272 + c16 * 16,
                      srcH + (size_t)k * (HW * 2) + c16 * 16);
            cpasync16(dst + 34816 + k * 272 + c16 * 16,
                      srcL + (size_t)k * (HW * 2) + c16 * 16);
        }
        CP_COMMIT();
    };

    copyX(0, 0);

    const int lane = tid & 31;
    const int warp = tid >> 5;
    const int g = lane >> 2, tg = lane & 3;
    const int mg = warp >> 2;
    const int mbase = mg * 32;
    const int nbase = (warp & 3) * 32;
    const int laneoff = (lane & 15) * 272 + ((lane >> 4) << 4);

    float acc[2][4][4];
    #pragma unroll
    for (int mt = 0; mt < 2; ++mt)
        #pragma unroll
        for (int nt = 0; nt < 4; ++nt)
            #pragma unroll
            for (int q = 0; q < 4; ++q) acc[mt][nt][q] = 0.f;

    for (int kc = 0; kc < 4; ++kc) {
        CP_WAIT0();
        __syncthreads();
        if (kc < 3) copyX(kc + 1, (kc + 1) & 1);

        const u32 smXh = smX[kc & 1];
        const u32 smXl = smXh + 34816;

        #pragma unroll
        for (int ks = 0; ks < 8; ++ks) {
            const uint4* wp = (const uint4*)&g_w2pk[(kc * 8 + ks) * 2048 + mg * 512 + lane * 16];
            uint4 H0 = wp[0], H1 = wp[1], L0_ = wp[2], L1 = wp[3];
            u32 ah[2][4] = {{H0.x, H0.y, H0.z, H0.w}, {H1.x, H1.y, H1.z, H1.w}};
            u32 al[2][4] = {{L0_.x, L0_.y, L0_.z, L0_.w}, {L1.x, L1.y, L1.z, L1.w}};
            #pragma unroll
            for (int ntp = 0; ntp < 2; ++ntp) {
                int n0 = nbase + ntp * 16;
                u32 bh[4], bl[4];
                ldsm4t(bh[0], bh[1], bh[2], bh[3],
                       smXh + laneoff + ks * 16 * 272 + n0 * 2);
                ldsm4t(bl[0], bl[1], bl[2], bl[3],
                       smXl + laneoff + ks * 16 * 272 + n0 * 2);
                #pragma unroll
                for (int mt = 0; mt < 2; ++mt) {
                    mma16816(acc[mt][2 * ntp],     ah[mt], bh[0], bh[1]);
                    mma16816(acc[mt][2 * ntp + 1], ah[mt], bh[2], bh[3]);
                    mma16816(acc[mt][2 * ntp],     ah[mt], bl[0], bl[1]);
                    mma16816(acc[mt][2 * ntp + 1], ah[mt], bl[2], bl[3]);
                    mma16816(acc[mt][2 * ntp],     al[mt], bh[0], bh[1]);
                    mma16816(acc[mt][2 * ntp + 1], al[mt], bh[2], bh[3]);
                }
            }
        }
    }

    #pragma unroll
    for (int mt = 0; mt < 2; ++mt) {
        int r = mbase + mt * 16 + g;
        int o0 = r, o1 = r + 8;
        float bv0 = b2[o0], bv1 = b2[o1];
        float* p0 = &io[(size_t)(b * 128 + o0) * HW + pix];
        float* p1 = &io[(size_t)(b * 128 + o1) * HW + pix];
        #pragma unroll
        for (int nt = 0; nt < 4; ++nt) {
            int col = nbase + nt * 8 + tg * 2;
            float2 v0 = *(float2*)&p0[col];
            float2 v1 = *(float2*)&p1[col];
            v0.x += acc[mt][nt][0] + bv0;
            v0.y += acc[mt][nt][1] + bv0;
            v1.x += acc[mt][nt][2] + bv1;
            v1.y += acc[mt][nt][3] + bv1;
            *(float2*)&p0[col] = v0;
            *(float2*)&p1[col] = v1;
        }
    }
}

// ---------------------------------------------------------------------------
extern "C" void kernel_launch(void* const* d_in, const int* in_sizes, int n_in,
                              void* d_out, int out_size)
{
    const float* x    = (const float*)d_in[0];
    const float* l0   = (const float*)d_in[1];
    const float* n1w  = (const float*)d_in[2];
    const float* n1b  = (const float*)d_in[3];
    const float* n2w  = (const float*)d_in[4];
    const float* n2b  = (const float*)d_in[5];
    const float* qkvw = (const float*)d_in[6];
    const float* gw   = (const float*)d_in[7];
    const float* gb   = (const float*)d_in[8];
    const float* pw   = (const float*)d_in[9];
    const float* pb   = (const float*)d_in[10];
    const float* w1   = (const float*)d_in[11];
    const float* b1   = (const float*)d_in[12];
    const float* dw   = (const float*)d_in[13];
    const float* dwb  = (const float*)d_in[14];
    const float* w2   = (const float*)d_in[15];
    const float* b2   = (const float*)d_in[16];
    float* out = (float*)d_out;

    cudaFuncSetAttribute(k1_attn, cudaFuncAttributeMaxDynamicSharedMemorySize, SM1_BYTES);
    cudaFuncSetAttribute(k2_ffn1, cudaFuncAttributeMaxDynamicSharedMemorySize, SM2_BYTES);
    cudaFuncSetAttribute(k4_ffn2, cudaFuncAttributeMaxDynamicSharedMemorySize, SM4_BYTES);

    k0_prep<<<768, 256>>>(w1, w2, qkvw, pw);
    k1_attn<<<4096, 512, SM1_BYTES>>>(x, l0, n1w, n1b, gw, gb, pb, out);
    k2_ffn1<<<2048, 512, SM2_BYTES>>>(out, n2w, n2b, b1);
    k3_dw<<<131072, 256>>>(dw, dwb);
    k4_ffn2<<<2048, 512, SM4_BYTES>>>(b2, out);
}